// round 3
// baseline (speedup 1.0000x reference)
#include <cuda_runtime.h>

// ---------------------------------------------------------------------------
// RadarSecondStageGenerator: with h0 == 0 the TrajGRU flow path is dead code.
// Live math:  x = conv3x3(in24 -> 8); i2h = conv3x3(x -> 24);
//             r=sig(i_r+br), u=sig(i_u+bu), m=leaky(i_m+r*bm), h=(1-u)*m;
//             out = conv1x1(h -> 12).
// Fully fused, one block per 32x32 tile per batch image.
// FIX vs R1: x halo values outside the global 128x128 image must be ZERO
// (conv zero-padding of the second conv), not computed from padded input.
// ---------------------------------------------------------------------------

#define THREADS 384
#define TILE 32

// shared memory layout (in floats)
#define IN_S_OFF   0                        // [24][36][36] input tile + halo2 (+8 pad)
#define IN_S_SIZE  (24*36*36 + 8)
#define X_S_OFF    (IN_S_OFF + IN_S_SIZE)   // [8][34][36]  x tile + halo1 (stride 36)
#define X_S_SIZE   (8*34*36)
#define WCIN_OFF   (X_S_OFF + X_S_SIZE)     // [ci=24][k=9][co=8]
#define WI2H_OFF   (WCIN_OFF + 1728)        // [ci=8][k=9][o=24]
#define WOUT_OFF   (WI2H_OFF + 1728)        // [t=12][c=8]
#define BCIN_OFF   (WOUT_OFF + 96)
#define BI2H_OFF   (BCIN_OFF + 8)
#define BRET_OFF   (BI2H_OFF + 24)
#define BOUT_OFF   (BRET_OFF + 24)
#define SMEM_FLOATS (BOUT_OFF + 12)
#define SMEM_BYTES (SMEM_FLOATS * 4)

__device__ __forceinline__ float sigmoidf_(float x) {
    return __fdividef(1.0f, 1.0f + __expf(-x));
}

__global__ void __launch_bounds__(THREADS)
radar2nd_fused_kernel(const float* __restrict__ radar,
                      const float* __restrict__ pred,
                      const float* __restrict__ w_cin,
                      const float* __restrict__ b_cin,
                      const float* __restrict__ w_i2h,
                      const float* __restrict__ b_i2h,
                      const float* __restrict__ b_ret,
                      const float* __restrict__ w_out,
                      const float* __restrict__ b_out,
                      float* __restrict__ out)
{
    extern __shared__ float sm[];
    float* in_s   = sm + IN_S_OFF;
    float* x_s    = sm + X_S_OFF;
    float* wcin_s = sm + WCIN_OFF;
    float* wi2h_s = sm + WI2H_OFF;
    float* wout_s = sm + WOUT_OFF;
    float* bcin_s = sm + BCIN_OFF;
    float* bi2h_s = sm + BI2H_OFF;
    float* bret_s = sm + BRET_OFF;
    float* bout_s = sm + BOUT_OFF;

    const int tid = threadIdx.x;
    const int b   = blockIdx.z;
    const int ty0 = blockIdx.y * TILE;
    const int tx0 = blockIdx.x * TILE;

    // ---------------- phase 0: stage + reorder weights into smem ----------
    // wcin_s[((ci*3+ky)*3+kx)*8 + co] = w_cin[((co*24+ci)*3+ky)*3+kx]
    for (int i = tid; i < 1728; i += THREADS) {
        int co = i & 7;
        int r  = i >> 3;
        int ci = r / 9;
        int k  = r - ci * 9;
        wcin_s[i] = w_cin[(co * 24 + ci) * 9 + k];
    }
    // wi2h_s[(ci*9 + k)*24 + o] = w_i2h[(o*8+ci)*9+k]
    for (int i = tid; i < 1728; i += THREADS) {
        int o  = i % 24;
        int r  = i / 24;
        int ci = r / 9;
        int k  = r - ci * 9;
        wi2h_s[i] = w_i2h[(o * 8 + ci) * 9 + k];
    }
    if (tid < 96) wout_s[tid] = w_out[tid];
    if (tid < 8)  bcin_s[tid] = b_cin[tid];
    if (tid < 24) bi2h_s[tid] = b_i2h[tid];
    if (tid < 24) bret_s[tid] = b_ret[tid];
    if (tid < 12) bout_s[tid] = b_out[tid];

    // ---------------- phase 1: load input tile (24ch, 36x36, zero-pad) ----
    for (int i = tid; i < 24 * 36 * 36; i += THREADS) {
        int xx = i % 36;
        int r  = i / 36;
        int yy = r % 36;
        int ch = r / 36;
        int gy = ty0 + yy - 2;
        int gx = tx0 + xx - 2;
        float v = 0.0f;
        if ((unsigned)gy < 128u && (unsigned)gx < 128u) {
            const float* src = (ch < 12) ? radar : pred;
            int c = (ch < 12) ? ch : ch - 12;
            v = __ldg(&src[((b * 12 + c) << 14) + (gy << 7) + gx]);
        }
        in_s[i] = v;
    }
    __syncthreads();

    // ---------------- phase 2: x = conv3x3(24 -> 8) on 34x34 region -------
    // region storage rows 0..33 (= out rows -1..32), 9 strips of 4 cols
    if (tid < 306) {
        const int row = tid / 9;
        const int xs  = (tid - row * 9) * 4;

        float acc[8][4];
        #pragma unroll
        for (int co = 0; co < 8; co++) {
            float bv = bcin_s[co];
            #pragma unroll
            for (int px = 0; px < 4; px++) acc[co][px] = bv;
        }

        #pragma unroll 1
        for (int ci = 0; ci < 24; ci++) {
            #pragma unroll
            for (int dy = 0; dy < 3; dy++) {
                const float* ap = &in_s[(ci * 36 + row + dy) * 36 + xs];
                float4 a03 = *(const float4*)ap;
                float2 a45 = *(const float2*)(ap + 4);
                float av[6] = {a03.x, a03.y, a03.z, a03.w, a45.x, a45.y};
                #pragma unroll
                for (int dx = 0; dx < 3; dx++) {
                    const float* wp = &wcin_s[((ci * 3 + dy) * 3 + dx) * 8];
                    float4 w0 = *(const float4*)wp;
                    float4 w1 = *(const float4*)(wp + 4);
                    float wv[8] = {w0.x, w0.y, w0.z, w0.w, w1.x, w1.y, w1.z, w1.w};
                    #pragma unroll
                    for (int co = 0; co < 8; co++) {
                        #pragma unroll
                        for (int px = 0; px < 4; px++)
                            acc[co][px] = fmaf(av[dx + px], wv[co], acc[co][px]);
                    }
                }
            }
        }

        // Store; x outside the global image is ZERO (second conv's padding).
        const int gyr = ty0 + row - 1;
        const bool rin = (unsigned)gyr < 128u;
        #pragma unroll
        for (int px = 0; px < 4; px++) {
            int c = xs + px;
            if (c < 34) {
                const int gxc = tx0 + c - 1;
                const bool inb = rin && ((unsigned)gxc < 128u);
                #pragma unroll
                for (int co = 0; co < 8; co++)
                    x_s[(co * 34 + row) * 36 + c] = inb ? acc[co][px] : 0.0f;
            }
        }
    }
    __syncthreads();

    // ---------------- phase 3: i2h conv3x3(8 -> 24) + gates + conv1x1 -----
    if (tid < 256) {
        const int row = tid >> 3;          // 0..31 tile row
        const int xs  = (tid & 7) * 4;     // 0..28 tile col base

        float acc[24][4];
        #pragma unroll
        for (int o = 0; o < 24; o++) {
            float bv = bi2h_s[o];
            #pragma unroll
            for (int px = 0; px < 4; px++) acc[o][px] = bv;
        }

        #pragma unroll 1
        for (int ci = 0; ci < 8; ci++) {
            #pragma unroll
            for (int dy = 0; dy < 3; dy++) {
                const float* ap = &x_s[(ci * 34 + row + dy) * 36 + xs];
                float4 a03 = *(const float4*)ap;
                float2 a45 = *(const float2*)(ap + 4);
                float av[6] = {a03.x, a03.y, a03.z, a03.w, a45.x, a45.y};
                #pragma unroll
                for (int dx = 0; dx < 3; dx++) {
                    const float* wp = &wi2h_s[(ci * 9 + dy * 3 + dx) * 24];
                    float wv[24];
                    #pragma unroll
                    for (int q = 0; q < 6; q++) {
                        float4 w4 = *(const float4*)(wp + q * 4);
                        wv[q * 4 + 0] = w4.x; wv[q * 4 + 1] = w4.y;
                        wv[q * 4 + 2] = w4.z; wv[q * 4 + 3] = w4.w;
                    }
                    #pragma unroll
                    for (int o = 0; o < 24; o++) {
                        #pragma unroll
                        for (int px = 0; px < 4; px++)
                            acc[o][px] = fmaf(av[dx + px], wv[o], acc[o][px]);
                    }
                }
            }
        }

        // gates (h2h from h0==0 is just b_ret broadcast)
        float h[8][4];
        #pragma unroll
        for (int c = 0; c < 8; c++) {
            float br = bret_s[c];
            float bu = bret_s[8 + c];
            float bm = bret_s[16 + c];
            #pragma unroll
            for (int px = 0; px < 4; px++) {
                float rg = sigmoidf_(acc[c][px] + br);
                float ug = sigmoidf_(acc[8 + c][px] + bu);
                float mm = fmaf(rg, bm, acc[16 + c][px]);
                mm = (mm >= 0.0f) ? mm : 0.2f * mm;
                h[c][px] = (1.0f - ug) * mm;
            }
        }

        // conv1x1 (8 -> 12) + store
        const int gy  = ty0 + row;
        const int gx0 = tx0 + xs;
        float* op = out + ((b * 12) << 14) + (gy << 7) + gx0;
        #pragma unroll
        for (int t = 0; t < 12; t++) {
            float o0 = bout_s[t], o1 = o0, o2 = o0, o3 = o0;
            #pragma unroll
            for (int c = 0; c < 8; c++) {
                float w = wout_s[t * 8 + c];
                o0 = fmaf(w, h[c][0], o0);
                o1 = fmaf(w, h[c][1], o1);
                o2 = fmaf(w, h[c][2], o2);
                o3 = fmaf(w, h[c][3], o3);
            }
            *(float4*)(op + (t << 14)) = make_float4(o0, o1, o2, o3);
        }
    }
}

extern "C" void kernel_launch(void* const* d_in, const int* in_sizes, int n_in,
                              void* d_out, int out_size)
{
    const float* radar = (const float*)d_in[0];   // (32,12,1,128,128)
    const float* pred  = (const float*)d_in[1];   // (32,12,1,128,128)
    const float* w_cin = (const float*)d_in[2];   // (8,24,3,3)
    const float* b_cin = (const float*)d_in[3];   // (8,)
    const float* w_i2h = (const float*)d_in[4];   // (24,8,3,3)
    const float* b_i2h = (const float*)d_in[5];   // (24,)
    // d_in[6..12]: flow-path params + w_ret -> dead code with h0 == 0
    const float* b_ret = (const float*)d_in[13];  // (24,)
    const float* w_out = (const float*)d_in[14];  // (12,8,1,1)
    const float* b_out = (const float*)d_in[15];  // (12,)
    float* out = (float*)d_out;                   // (32,12,1,128,128)

    cudaFuncSetAttribute(radar2nd_fused_kernel,
                         cudaFuncAttributeMaxDynamicSharedMemorySize, SMEM_BYTES);

    dim3 grid(128 / TILE, 128 / TILE, 32);        // (4,4,32) = 512 blocks
    radar2nd_fused_kernel<<<grid, THREADS, SMEM_BYTES>>>(
        radar, pred, w_cin, b_cin, w_i2h, b_i2h, b_ret, w_out, b_out, out);
}

// round 4
// speedup vs baseline: 1.0812x; 1.0812x over previous
#include <cuda_runtime.h>

// ---------------------------------------------------------------------------
// RadarSecondStageGenerator, fused. R4: packed f32x2 FFMA (FFMA2) in both
// conv phases, pairing over the output-channel dimension so weight pairs are
// contiguous LDS loads and only activations need (a,a) duplication.
// ---------------------------------------------------------------------------

#define THREADS 384
#define TILE 32

// shared memory layout (in floats)
#define IN_S_OFF   0                        // [24][36][36] input tile + halo2 (+8 pad)
#define IN_S_SIZE  (24*36*36 + 8)
#define X_S_OFF    (IN_S_OFF + IN_S_SIZE)   // [8][34][36]  x tile + halo1 (stride 36)
#define X_S_SIZE   (8*34*36)
#define WCIN_OFF   (X_S_OFF + X_S_SIZE)     // [ci=24][k=9][co=8]
#define WI2H_OFF   (WCIN_OFF + 1728)        // [ci=8][k=9][o=24]
#define WOUT_OFF   (WI2H_OFF + 1728)        // [t=12][c=8]
#define BCIN_OFF   (WOUT_OFF + 96)
#define BI2H_OFF   (BCIN_OFF + 8)
#define BRET_OFF   (BI2H_OFF + 24)
#define BOUT_OFF   (BRET_OFF + 24)
#define SMEM_FLOATS (BOUT_OFF + 12)
#define SMEM_BYTES (SMEM_FLOATS * 4)

typedef unsigned long long u64;

__device__ __forceinline__ float sigmoidf_(float x) {
    return __fdividef(1.0f, 1.0f + __expf(-x));
}

__device__ __forceinline__ u64 pk2(float lo, float hi) {
    u64 r; asm("mov.b64 %0, {%1, %2};" : "=l"(r) : "f"(lo), "f"(hi)); return r;
}
__device__ __forceinline__ u64 ffma2(u64 a, u64 b, u64 c) {
    u64 d; asm("fma.rn.f32x2 %0, %1, %2, %3;" : "=l"(d) : "l"(a), "l"(b), "l"(c)); return d;
}
__device__ __forceinline__ float2 upk2(u64 v) {
    float2 f; asm("mov.b64 {%0, %1}, %2;" : "=f"(f.x), "=f"(f.y) : "l"(v)); return f;
}

__global__ void __launch_bounds__(THREADS)
radar2nd_fused_kernel(const float* __restrict__ radar,
                      const float* __restrict__ pred,
                      const float* __restrict__ w_cin,
                      const float* __restrict__ b_cin,
                      const float* __restrict__ w_i2h,
                      const float* __restrict__ b_i2h,
                      const float* __restrict__ b_ret,
                      const float* __restrict__ w_out,
                      const float* __restrict__ b_out,
                      float* __restrict__ out)
{
    extern __shared__ float sm[];
    float* in_s   = sm + IN_S_OFF;
    float* x_s    = sm + X_S_OFF;
    float* wcin_s = sm + WCIN_OFF;
    float* wi2h_s = sm + WI2H_OFF;
    float* wout_s = sm + WOUT_OFF;
    float* bcin_s = sm + BCIN_OFF;
    float* bi2h_s = sm + BI2H_OFF;
    float* bret_s = sm + BRET_OFF;
    float* bout_s = sm + BOUT_OFF;

    const int tid = threadIdx.x;
    const int b   = blockIdx.z;
    const int ty0 = blockIdx.y * TILE;
    const int tx0 = blockIdx.x * TILE;

    // ---------------- phase 0: stage + reorder weights into smem ----------
    // wcin_s[((ci*3+ky)*3+kx)*8 + co] = w_cin[((co*24+ci)*3+ky)*3+kx]
    for (int i = tid; i < 1728; i += THREADS) {
        int co = i & 7;
        int r  = i >> 3;
        int ci = r / 9;
        int k  = r - ci * 9;
        wcin_s[i] = w_cin[(co * 24 + ci) * 9 + k];
    }
    // wi2h_s[(ci*9 + k)*24 + o] = w_i2h[(o*8+ci)*9+k]
    for (int i = tid; i < 1728; i += THREADS) {
        int o  = i % 24;
        int r  = i / 24;
        int ci = r / 9;
        int k  = r - ci * 9;
        wi2h_s[i] = w_i2h[(o * 8 + ci) * 9 + k];
    }
    if (tid < 96) wout_s[tid] = w_out[tid];
    if (tid < 8)  bcin_s[tid] = b_cin[tid];
    if (tid < 24) bi2h_s[tid] = b_i2h[tid];
    if (tid < 24) bret_s[tid] = b_ret[tid];
    if (tid < 12) bout_s[tid] = b_out[tid];

    // ---------------- phase 1: load input tile (24ch, 36x36, zero-pad) ----
    for (int i = tid; i < 24 * 36 * 36; i += THREADS) {
        int xx = i % 36;
        int r  = i / 36;
        int yy = r % 36;
        int ch = r / 36;
        int gy = ty0 + yy - 2;
        int gx = tx0 + xx - 2;
        float v = 0.0f;
        if ((unsigned)gy < 128u && (unsigned)gx < 128u) {
            const float* src = (ch < 12) ? radar : pred;
            int c = (ch < 12) ? ch : ch - 12;
            v = __ldg(&src[((b * 12 + c) << 14) + (gy << 7) + gx]);
        }
        in_s[i] = v;
    }
    __syncthreads();

    // ---------------- phase 2: x = conv3x3(24 -> 8) on 34x34 region -------
    // f32x2: accumulators packed over output-channel pairs (co, co+1).
    if (tid < 306) {
        const int row = tid / 9;
        const int xs  = (tid - row * 9) * 4;

        u64 acc2[4][4];                     // [co_pair][px]
        #pragma unroll
        for (int cp = 0; cp < 4; cp++) {
            u64 bv = pk2(bcin_s[2 * cp], bcin_s[2 * cp + 1]);
            #pragma unroll
            for (int px = 0; px < 4; px++) acc2[cp][px] = bv;
        }

        #pragma unroll 1
        for (int ci = 0; ci < 24; ci++) {
            #pragma unroll
            for (int dy = 0; dy < 3; dy++) {
                const float* ap = &in_s[(ci * 36 + row + dy) * 36 + xs];
                float4 a03 = *(const float4*)ap;
                float2 a45 = *(const float2*)(ap + 4);
                u64 ad[6];
                ad[0] = pk2(a03.x, a03.x); ad[1] = pk2(a03.y, a03.y);
                ad[2] = pk2(a03.z, a03.z); ad[3] = pk2(a03.w, a03.w);
                ad[4] = pk2(a45.x, a45.x); ad[5] = pk2(a45.y, a45.y);
                #pragma unroll
                for (int dx = 0; dx < 3; dx++) {
                    const u64* wp2 = (const u64*)&wcin_s[((ci * 3 + dy) * 3 + dx) * 8];
                    ulonglong2 wA = *(const ulonglong2*)(wp2);
                    ulonglong2 wB = *(const ulonglong2*)(wp2 + 2);
                    u64 wv[4] = {wA.x, wA.y, wB.x, wB.y};
                    #pragma unroll
                    for (int cp = 0; cp < 4; cp++) {
                        #pragma unroll
                        for (int px = 0; px < 4; px++)
                            acc2[cp][px] = ffma2(ad[dx + px], wv[cp], acc2[cp][px]);
                    }
                }
            }
        }

        // Store; x outside the global image is ZERO (second conv's padding).
        const int gyr = ty0 + row - 1;
        const bool rin = (unsigned)gyr < 128u;
        #pragma unroll
        for (int px = 0; px < 4; px++) {
            int c = xs + px;
            if (c < 34) {
                const int gxc = tx0 + c - 1;
                const bool inb = rin && ((unsigned)gxc < 128u);
                #pragma unroll
                for (int cp = 0; cp < 4; cp++) {
                    float2 v = upk2(acc2[cp][px]);
                    x_s[((2 * cp + 0) * 34 + row) * 36 + c] = inb ? v.x : 0.0f;
                    x_s[((2 * cp + 1) * 34 + row) * 36 + c] = inb ? v.y : 0.0f;
                }
            }
        }
    }
    __syncthreads();

    // ---------------- phase 3: i2h conv3x3(8 -> 24) + gates + conv1x1 -----
    if (tid < 256) {
        const int row = tid >> 3;          // 0..31 tile row
        const int xs  = (tid & 7) * 4;     // 0..28 tile col base

        u64 acc2[12][4];                   // [o_pair][px]
        #pragma unroll
        for (int op = 0; op < 12; op++) {
            u64 bv = pk2(bi2h_s[2 * op], bi2h_s[2 * op + 1]);
            #pragma unroll
            for (int px = 0; px < 4; px++) acc2[op][px] = bv;
        }

        #pragma unroll 1
        for (int ci = 0; ci < 8; ci++) {
            #pragma unroll
            for (int dy = 0; dy < 3; dy++) {
                const float* ap = &x_s[(ci * 34 + row + dy) * 36 + xs];
                float4 a03 = *(const float4*)ap;
                float2 a45 = *(const float2*)(ap + 4);
                u64 ad[6];
                ad[0] = pk2(a03.x, a03.x); ad[1] = pk2(a03.y, a03.y);
                ad[2] = pk2(a03.z, a03.z); ad[3] = pk2(a03.w, a03.w);
                ad[4] = pk2(a45.x, a45.x); ad[5] = pk2(a45.y, a45.y);
                #pragma unroll
                for (int dx = 0; dx < 3; dx++) {
                    const u64* wp2 = (const u64*)&wi2h_s[(ci * 9 + dy * 3 + dx) * 24];
                    u64 wv[12];
                    #pragma unroll
                    for (int q = 0; q < 6; q++) {
                        ulonglong2 w2 = *(const ulonglong2*)(wp2 + q * 2);
                        wv[q * 2 + 0] = w2.x;
                        wv[q * 2 + 1] = w2.y;
                    }
                    #pragma unroll
                    for (int op = 0; op < 12; op++) {
                        #pragma unroll
                        for (int px = 0; px < 4; px++)
                            acc2[op][px] = ffma2(ad[dx + px], wv[op], acc2[op][px]);
                    }
                }
            }
        }

        // gates (h2h from h0==0 is just b_ret broadcast); channel pairs
        // (c,c+1) stay aligned: r at pair cp, u at pair 4+cp, m at pair 8+cp.
        float h[8][4];
        #pragma unroll
        for (int cp = 0; cp < 4; cp++) {
            float br0 = bret_s[2 * cp],      br1 = bret_s[2 * cp + 1];
            float bu0 = bret_s[8 + 2 * cp],  bu1 = bret_s[8 + 2 * cp + 1];
            float bm0 = bret_s[16 + 2 * cp], bm1 = bret_s[16 + 2 * cp + 1];
            #pragma unroll
            for (int px = 0; px < 4; px++) {
                float2 ir = upk2(acc2[cp][px]);
                float2 iu = upk2(acc2[4 + cp][px]);
                float2 im = upk2(acc2[8 + cp][px]);
                float rg0 = sigmoidf_(ir.x + br0);
                float rg1 = sigmoidf_(ir.y + br1);
                float ug0 = sigmoidf_(iu.x + bu0);
                float ug1 = sigmoidf_(iu.y + bu1);
                float m0 = fmaf(rg0, bm0, im.x);
                float m1 = fmaf(rg1, bm1, im.y);
                m0 = (m0 >= 0.0f) ? m0 : 0.2f * m0;
                m1 = (m1 >= 0.0f) ? m1 : 0.2f * m1;
                h[2 * cp + 0][px] = (1.0f - ug0) * m0;
                h[2 * cp + 1][px] = (1.0f - ug1) * m1;
            }
        }

        // conv1x1 (8 -> 12) + store; pack px pairs for f32x2 too
        const int gy  = ty0 + row;
        const int gx0 = tx0 + xs;
        float* op_ = out + ((b * 12) << 14) + (gy << 7) + gx0;
        u64 hp[8][2];
        #pragma unroll
        for (int c = 0; c < 8; c++) {
            hp[c][0] = pk2(h[c][0], h[c][1]);
            hp[c][1] = pk2(h[c][2], h[c][3]);
        }
        #pragma unroll
        for (int t = 0; t < 12; t++) {
            u64 o01 = pk2(bout_s[t], bout_s[t]);
            u64 o23 = o01;
            #pragma unroll
            for (int c = 0; c < 8; c++) {
                float w = wout_s[t * 8 + c];
                u64 w2 = pk2(w, w);
                o01 = ffma2(hp[c][0], w2, o01);
                o23 = ffma2(hp[c][1], w2, o23);
            }
            float2 a = upk2(o01), bq = upk2(o23);
            *(float4*)(op_ + (t << 14)) = make_float4(a.x, a.y, bq.x, bq.y);
        }
    }
}

extern "C" void kernel_launch(void* const* d_in, const int* in_sizes, int n_in,
                              void* d_out, int out_size)
{
    const float* radar = (const float*)d_in[0];   // (32,12,1,128,128)
    const float* pred  = (const float*)d_in[1];   // (32,12,1,128,128)
    const float* w_cin = (const float*)d_in[2];   // (8,24,3,3)
    const float* b_cin = (const float*)d_in[3];   // (8,)
    const float* w_i2h = (const float*)d_in[4];   // (24,8,3,3)
    const float* b_i2h = (const float*)d_in[5];   // (24,)
    // d_in[6..12]: flow-path params + w_ret -> dead code with h0 == 0
    const float* b_ret = (const float*)d_in[13];  // (24,)
    const float* w_out = (const float*)d_in[14];  // (12,8,1,1)
    const float* b_out = (const float*)d_in[15];  // (12,)
    float* out = (float*)d_out;                   // (32,12,1,128,128)

    cudaFuncSetAttribute(radar2nd_fused_kernel,
                         cudaFuncAttributeMaxDynamicSharedMemorySize, SMEM_BYTES);

    dim3 grid(128 / TILE, 128 / TILE, 32);        // (4,4,32) = 512 blocks
    radar2nd_fused_kernel<<<grid, THREADS, SMEM_BYTES>>>(
        radar, pred, w_cin, b_cin, w_i2h, b_i2h, b_ret, w_out, b_out, out);
}

// round 6
// speedup vs baseline: 1.1369x; 1.0515x over previous
#include <cuda_runtime.h>

// ---------------------------------------------------------------------------
// RadarSecondStageGenerator, fused. R5: 16x32 tiles -> smem ~104KB/CTA and
// regs<=128 so 2 CTAs/SM (occupancy 2x vs R4). FFMA2 math kept from R4.
// ---------------------------------------------------------------------------

#define THREADS 256
#define TX 32
#define TY 16

// shared memory layout (in floats)
#define IN_S_OFF   0                        // [24][20][36] input tile + halo2
#define IN_S_SIZE  (24*20*36 + 8)
#define X_S_OFF    (IN_S_OFF + IN_S_SIZE)   // [8][18][36]  x tile + halo1
#define X_S_SIZE   (8*18*36)
#define WCIN_OFF   (X_S_OFF + X_S_SIZE)     // [ci=24][k=9][co=8]
#define WI2H_OFF   (WCIN_OFF + 1728)        // [ci=8][k=9][o=24]
#define WOUT_OFF   (WI2H_OFF + 1728)        // [t=12][c=8]
#define BCIN_OFF   (WOUT_OFF + 96)
#define BI2H_OFF   (BCIN_OFF + 8)
#define BRET_OFF   (BI2H_OFF + 24)
#define BOUT_OFF   (BRET_OFF + 24)
#define SMEM_FLOATS (BOUT_OFF + 12)
#define SMEM_BYTES (SMEM_FLOATS * 4)

typedef unsigned long long u64;

__device__ __forceinline__ float sigmoidf_(float x) {
    return __fdividef(1.0f, 1.0f + __expf(-x));
}

__device__ __forceinline__ u64 pk2(float lo, float hi) {
    u64 r; asm("mov.b64 %0, {%1, %2};" : "=l"(r) : "f"(lo), "f"(hi)); return r;
}
__device__ __forceinline__ u64 ffma2(u64 a, u64 b, u64 c) {
    u64 d; asm("fma.rn.f32x2 %0, %1, %2, %3;" : "=l"(d) : "l"(a), "l"(b), "l"(c)); return d;
}
__device__ __forceinline__ float2 upk2(u64 v) {
    float2 f; asm("mov.b64 {%0, %1}, %2;" : "=f"(f.x), "=f"(f.y) : "l"(v)); return f;
}

__global__ void __launch_bounds__(THREADS, 2)
radar2nd_fused_kernel(const float* __restrict__ radar,
                      const float* __restrict__ pred,
                      const float* __restrict__ w_cin,
                      const float* __restrict__ b_cin,
                      const float* __restrict__ w_i2h,
                      const float* __restrict__ b_i2h,
                      const float* __restrict__ b_ret,
                      const float* __restrict__ w_out,
                      const float* __restrict__ b_out,
                      float* __restrict__ out)
{
    extern __shared__ float sm[];
    float* in_s   = sm + IN_S_OFF;
    float* x_s    = sm + X_S_OFF;
    float* wcin_s = sm + WCIN_OFF;
    float* wi2h_s = sm + WI2H_OFF;
    float* wout_s = sm + WOUT_OFF;
    float* bcin_s = sm + BCIN_OFF;
    float* bi2h_s = sm + BI2H_OFF;
    float* bret_s = sm + BRET_OFF;
    float* bout_s = sm + BOUT_OFF;

    const int tid = threadIdx.x;
    const int b   = blockIdx.z;
    const int ty0 = blockIdx.y * TY;
    const int tx0 = blockIdx.x * TX;

    // ---------------- phase 0: stage + reorder weights into smem ----------
    // wcin_s[((ci*3+ky)*3+kx)*8 + co] = w_cin[((co*24+ci)*3+ky)*3+kx]
    for (int i = tid; i < 1728; i += THREADS) {
        int co = i & 7;
        int r  = i >> 3;
        int ci = r / 9;
        int k  = r - ci * 9;
        wcin_s[i] = w_cin[(co * 24 + ci) * 9 + k];
    }
    // wi2h_s[(ci*9 + k)*24 + o] = w_i2h[(o*8+ci)*9+k]
    for (int i = tid; i < 1728; i += THREADS) {
        int o  = i % 24;
        int r  = i / 24;
        int ci = r / 9;
        int k  = r - ci * 9;
        wi2h_s[i] = w_i2h[(o * 8 + ci) * 9 + k];
    }
    if (tid < 96) wout_s[tid] = w_out[tid];
    if (tid < 8)  bcin_s[tid] = b_cin[tid];
    if (tid < 24) bi2h_s[tid] = b_i2h[tid];
    if (tid < 24) bret_s[tid] = b_ret[tid];
    if (tid < 12) bout_s[tid] = b_out[tid];

    // ---------------- phase 1: load input tile (24ch, 20x36, zero-pad) ----
    for (int i = tid; i < 24 * 20 * 36; i += THREADS) {
        int xx = i % 36;
        int r  = i / 36;
        int yy = r % 20;
        int ch = r / 20;
        int gy = ty0 + yy - 2;
        int gx = tx0 + xx - 2;
        float v = 0.0f;
        if ((unsigned)gy < 128u && (unsigned)gx < 128u) {
            const float* src = (ch < 12) ? radar : pred;
            int c = (ch < 12) ? ch : ch - 12;
            v = __ldg(&src[((b * 12 + c) << 14) + (gy << 7) + gx]);
        }
        in_s[i] = v;
    }
    __syncthreads();

    // ---------------- phase 2: x = conv3x3(24 -> 8) on 18x34 region -------
    // 3-px strips, 12 strips/row x 18 rows = 216 active threads.
    if (tid < 216) {
        const int row = tid / 12;
        const int xs  = (tid - row * 12) * 3;

        u64 acc2[4][3];                     // [co_pair][px]
        #pragma unroll
        for (int cp = 0; cp < 4; cp++) {
            u64 bv = pk2(bcin_s[2 * cp], bcin_s[2 * cp + 1]);
            #pragma unroll
            for (int px = 0; px < 3; px++) acc2[cp][px] = bv;
        }

        #pragma unroll 1
        for (int ci = 0; ci < 24; ci++) {
            #pragma unroll
            for (int dy = 0; dy < 3; dy++) {
                const float* ap = &in_s[(ci * 20 + row + dy) * 36 + xs];
                u64 ad[5];
                #pragma unroll
                for (int q = 0; q < 5; q++) { float a = ap[q]; ad[q] = pk2(a, a); }
                #pragma unroll
                for (int dx = 0; dx < 3; dx++) {
                    const u64* wp2 = (const u64*)&wcin_s[((ci * 3 + dy) * 3 + dx) * 8];
                    ulonglong2 wA = *(const ulonglong2*)(wp2);
                    ulonglong2 wB = *(const ulonglong2*)(wp2 + 2);
                    u64 wv[4] = {wA.x, wA.y, wB.x, wB.y};
                    #pragma unroll
                    for (int cp = 0; cp < 4; cp++) {
                        #pragma unroll
                        for (int px = 0; px < 3; px++)
                            acc2[cp][px] = ffma2(ad[dx + px], wv[cp], acc2[cp][px]);
                    }
                }
            }
        }

        // Store; x outside the global image is ZERO (second conv's padding).
        const int gyr = ty0 + row - 1;
        const bool rin = (unsigned)gyr < 128u;
        #pragma unroll
        for (int px = 0; px < 3; px++) {
            int c = xs + px;
            if (c < 34) {
                const int gxc = tx0 + c - 1;
                const bool inb = rin && ((unsigned)gxc < 128u);
                #pragma unroll
                for (int cp = 0; cp < 4; cp++) {
                    float2 v = upk2(acc2[cp][px]);
                    x_s[((2 * cp + 0) * 18 + row) * 36 + c] = inb ? v.x : 0.0f;
                    x_s[((2 * cp + 1) * 18 + row) * 36 + c] = inb ? v.y : 0.0f;
                }
            }
        }
    }
    __syncthreads();

    // ---------------- phase 3: i2h conv3x3(8 -> 24) + gates + conv1x1 -----
    // 2-px strips: 16 strips/row x 16 rows = all 256 threads active.
    {
        const int row = tid >> 4;          // 0..15 tile row
        const int xs  = (tid & 15) * 2;    // 0..30 tile col base

        u64 acc2[12][2];                   // [o_pair][px]
        #pragma unroll
        for (int op = 0; op < 12; op++) {
            u64 bv = pk2(bi2h_s[2 * op], bi2h_s[2 * op + 1]);
            #pragma unroll
            for (int px = 0; px < 2; px++) acc2[op][px] = bv;
        }

        #pragma unroll 1
        for (int ci = 0; ci < 8; ci++) {
            #pragma unroll
            for (int dy = 0; dy < 3; dy++) {
                const float* ap = &x_s[(ci * 18 + row + dy) * 36 + xs];
                float2 a01 = *(const float2*)ap;
                float2 a23 = *(const float2*)(ap + 2);
                u64 ad[4];
                ad[0] = pk2(a01.x, a01.x); ad[1] = pk2(a01.y, a01.y);
                ad[2] = pk2(a23.x, a23.x); ad[3] = pk2(a23.y, a23.y);
                #pragma unroll
                for (int dx = 0; dx < 3; dx++) {
                    const u64* wp2 = (const u64*)&wi2h_s[(ci * 9 + dy * 3 + dx) * 24];
                    u64 wv[12];
                    #pragma unroll
                    for (int q = 0; q < 6; q++) {
                        ulonglong2 w2 = *(const ulonglong2*)(wp2 + q * 2);
                        wv[q * 2 + 0] = w2.x;
                        wv[q * 2 + 1] = w2.y;
                    }
                    #pragma unroll
                    for (int op = 0; op < 12; op++) {
                        #pragma unroll
                        for (int px = 0; px < 2; px++)
                            acc2[op][px] = ffma2(ad[dx + px], wv[op], acc2[op][px]);
                    }
                }
            }
        }

        // gates (h2h from h0==0 is just b_ret broadcast); channel pairs
        // (c,c+1) stay aligned: r at pair cp, u at pair 4+cp, m at pair 8+cp.
        float h[8][2];
        #pragma unroll
        for (int cp = 0; cp < 4; cp++) {
            float br0 = bret_s[2 * cp],      br1 = bret_s[2 * cp + 1];
            float bu0 = bret_s[8 + 2 * cp],  bu1 = bret_s[8 + 2 * cp + 1];
            float bm0 = bret_s[16 + 2 * cp], bm1 = bret_s[16 + 2 * cp + 1];
            #pragma unroll
            for (int px = 0; px < 2; px++) {
                float2 ir = upk2(acc2[cp][px]);
                float2 iu = upk2(acc2[4 + cp][px]);
                float2 im = upk2(acc2[8 + cp][px]);
                float rg0 = sigmoidf_(ir.x + br0);
                float rg1 = sigmoidf_(ir.y + br1);
                float ug0 = sigmoidf_(iu.x + bu0);
                float ug1 = sigmoidf_(iu.y + bu1);
                float m0 = fmaf(rg0, bm0, im.x);
                float m1 = fmaf(rg1, bm1, im.y);
                m0 = (m0 >= 0.0f) ? m0 : 0.2f * m0;
                m1 = (m1 >= 0.0f) ? m1 : 0.2f * m1;
                h[2 * cp + 0][px] = (1.0f - ug0) * m0;
                h[2 * cp + 1][px] = (1.0f - ug1) * m1;
            }
        }

        // conv1x1 (8 -> 12) + store; pack px pair for f32x2
        const int gy  = ty0 + row;
        const int gx0 = tx0 + xs;
        float* op_ = out + ((b * 12) << 14) + (gy << 7) + gx0;
        u64 hp[8];
        #pragma unroll
        for (int c = 0; c < 8; c++) hp[c] = pk2(h[c][0], h[c][1]);
        #pragma unroll
        for (int t = 0; t < 12; t++) {
            u64 o01 = pk2(bout_s[t], bout_s[t]);
            #pragma unroll
            for (int c = 0; c < 8; c++) {
                float w = wout_s[t * 8 + c];
                o01 = ffma2(hp[c], pk2(w, w), o01);
            }
            float2 a = upk2(o01);
            *(float2*)(op_ + (t << 14)) = a;
        }
    }
}

extern "C" void kernel_launch(void* const* d_in, const int* in_sizes, int n_in,
                              void* d_out, int out_size)
{
    const float* radar = (const float*)d_in[0];   // (32,12,1,128,128)
    const float* pred  = (const float*)d_in[1];   // (32,12,1,128,128)
    const float* w_cin = (const float*)d_in[2];   // (8,24,3,3)
    const float* b_cin = (const float*)d_in[3];   // (8,)
    const float* w_i2h = (const float*)d_in[4];   // (24,8,3,3)
    const float* b_i2h = (const float*)d_in[5];   // (24,)
    // d_in[6..12]: flow-path params + w_ret -> dead code with h0 == 0
    const float* b_ret = (const float*)d_in[13];  // (24,)
    const float* w_out = (const float*)d_in[14];  // (12,8,1,1)
    const float* b_out = (const float*)d_in[15];  // (12,)
    float* out = (float*)d_out;                   // (32,12,1,128,128)

    cudaFuncSetAttribute(radar2nd_fused_kernel,
                         cudaFuncAttributeMaxDynamicSharedMemorySize, SMEM_BYTES);

    dim3 grid(128 / TX, 128 / TY, 32);            // (4,8,32) = 1024 blocks
    radar2nd_fused_kernel<<<grid, THREADS, SMEM_BYTES>>>(
        radar, pred, w_cin, b_cin, w_i2h, b_i2h, b_ret, w_out, b_out, out);
}